// round 7
// baseline (speedup 1.0000x reference)
#include <cuda_runtime.h>
#include <cstdint>
#include <math.h>

#define DB 32
#define DT 2048
#define DI 128
#define DH 256

// Scratch (allocation-free rule: __device__ globals). Force 256B alignment so
// float4 / 128-bit LDG/STG on these are legal.
__device__ __align__(256) float g_xb[DB * DT * DH];
__device__ __align__(256) float g_hs[DB * DT * DH];

// ---------------- PTX helpers ----------------
__device__ __forceinline__ uint32_t smem_u32(const void* p) {
    return (uint32_t)__cvta_generic_to_shared(p);
}
__device__ __forceinline__ uint32_t mapa_u32(uint32_t a, uint32_t rank) {
    uint32_t r;
    asm volatile("mapa.shared::cluster.u32 %0, %1, %2;" : "=r"(r) : "r"(a), "r"(rank));
    return r;
}
__device__ __forceinline__ void st_cluster_f32(uint32_t a, float v) {
    asm volatile("st.shared::cluster.f32 [%0], %1;" :: "r"(a), "f"(v) : "memory");
}
__device__ __forceinline__ void cluster_arrive() {
    asm volatile("barrier.cluster.arrive.aligned;" ::: "memory");  // release
}
__device__ __forceinline__ void cluster_wait() {
    asm volatile("barrier.cluster.wait.aligned;" ::: "memory");    // acquire
}

// ---------------- Tiled fp32 GEMM: out[M,N] = in[M,K] @ W[K,N] ----------------
// BM=BN=BK=64, 256 threads, 4x4 register microtile. K_TOTAL is also lda of `in`.
template<int K_TOTAL>
__device__ __forceinline__ void gemm_body(const float* __restrict__ in,
                                          const float* __restrict__ W,
                                          float* __restrict__ out, int N)
{
    __shared__ __align__(16) float sA[64][68];  // transposed: sA[k][m], pad 68 (16B-aligned rows)
    __shared__ __align__(16) float sB[64][64];  // sB[k][n]

    const int tx = threadIdx.x & 15;
    const int ty = threadIdx.x >> 4;
    const int mBase = blockIdx.y * 64;
    const int nBase = blockIdx.x * 64;

    float acc[4][4] = {};

    for (int k0 = 0; k0 < K_TOTAL; k0 += 64) {
        // Load A tile (64m x 64k), store transposed into sA[k][m]
        #pragma unroll
        for (int it = 0; it < 4; ++it) {
            int idx = threadIdx.x + it * 256;   // 0..1023 float4s
            int m  = idx >> 4;                  // 16 float4 per row
            int kq = idx & 15;
            float4 v = *(const float4*)(in + (size_t)(mBase + m) * K_TOTAL + k0 + kq * 4);
            sA[kq * 4 + 0][m] = v.x;
            sA[kq * 4 + 1][m] = v.y;
            sA[kq * 4 + 2][m] = v.z;
            sA[kq * 4 + 3][m] = v.w;
        }
        // Load B tile (64k x 64n)
        #pragma unroll
        for (int it = 0; it < 4; ++it) {
            int idx = threadIdx.x + it * 256;
            int k  = idx >> 4;
            int nq = idx & 15;
            *(float4*)(&sB[k][nq * 4]) =
                *(const float4*)(W + (size_t)(k0 + k) * N + nBase + nq * 4);
        }
        __syncthreads();

        #pragma unroll 8
        for (int k = 0; k < 64; ++k) {
            float4 a4 = *(const float4*)(&sA[k][ty * 4]);
            float4 b4 = *(const float4*)(&sB[k][tx * 4]);
            float av[4] = {a4.x, a4.y, a4.z, a4.w};
            float bv[4] = {b4.x, b4.y, b4.z, b4.w};
            #pragma unroll
            for (int i = 0; i < 4; ++i)
                #pragma unroll
                for (int j = 0; j < 4; ++j)
                    acc[i][j] = fmaf(av[i], bv[j], acc[i][j]);
        }
        __syncthreads();
    }

    #pragma unroll
    for (int i = 0; i < 4; ++i) {
        float4 v = make_float4(acc[i][0], acc[i][1], acc[i][2], acc[i][3]);
        *(float4*)(out + (size_t)(mBase + ty * 4 + i) * N + nBase + tx * 4) = v;
    }
}

__global__ void __launch_bounds__(256, 2)
gemm_xb_kernel(const float* __restrict__ x, const float* __restrict__ Bm)
{
    gemm_body<DI>(x, Bm, g_xb, DH);          // [B*T,128] @ [128,256] -> g_xb
}

__global__ void __launch_bounds__(256, 2)
gemm_out_kernel(const float* __restrict__ C, float* __restrict__ out)
{
    gemm_body<DH>(g_hs, C, out, DH);         // [B*T,256] @ [256,256] -> out
}

// ---------------- Scan: one 4-CTA cluster per batch ----------------
// CTA rank r owns output columns [64r, 64r+64). Its 256x64 slice of A lives in
// registers (512 threads x 32 floats). Per step:
//   1) every thread: 32-length partial dot of h (smem, warp-broadcast LDS.128)
//      with its A registers -> part[kc][j]
//   2) __syncthreads; producers (tid<64) reduce 8 partials, add xb, tanh
//   3) producers push h_next[colg] into ALL 4 CTAs' h_buf[s^1] via
//      st.shared::cluster (write slot != read slot, so no conflict)
//   4) ONE barrier.cluster arrive/wait pair: release-publishes the remote
//      writes AND guarantees slot s is fully consumed before step t+1
//      overwrites it. Executed every step (incl. the last, where the push is
//      skipped) => all remote SMEM traffic quiesced before any CTA exits.
__global__ void __launch_bounds__(512, 1) __cluster_dims__(4, 1, 1)
scan_kernel(const float* __restrict__ A)
{
    __shared__ __align__(16) float h_buf[2][DH];
    __shared__ float part[8][64];

    const int tid = threadIdx.x;
    const int j   = tid & 63;
    const int kc  = tid >> 6;                 // 0..7, chunk of 32 k-values
    uint32_t rank;
    asm("mov.u32 %0, %%cluster_ctarank;" : "=r"(rank));
    const int batch = blockIdx.x >> 2;
    const int colg  = (int)rank * 64 + j;

    const uint32_t hb_a[2] = { smem_u32(&h_buf[0][0]), smem_u32(&h_buf[1][0]) };

    // h_0 = 0 (slot 0; slot 1 is fully written at t=0 before first read at t=1)
    for (int i = tid; i < DH; i += 512) h_buf[0][i] = 0.f;

    // Cache this CTA's A slice in registers: a_reg[i] = A[kc*32 + i][colg]
    float a_reg[32];
    #pragma unroll
    for (int i = 0; i < 32; ++i)
        a_reg[i] = A[(size_t)(kc * 32 + i) * DH + colg];

    // xb prefetch pipeline (depth 2), producer threads only
    const float* xb_b = g_xb + (size_t)batch * DT * DH + colg;
    float*       hs_b = g_hs + (size_t)batch * DT * DH + colg;
    float xb_buf[2] = {0.f, 0.f};
    if (tid < 64) {
        xb_buf[0] = __ldg(&xb_b[0]);
        xb_buf[1] = __ldg(&xb_b[(size_t)DH]);
    }

    __syncthreads();
    cluster_arrive(); cluster_wait();        // all CTAs ready before remote stores fly

    for (int t = 0; t < DT; ++t) {
        const int s = t & 1;

        // Partial dot over this thread's 32-k chunk (uniform address within a
        // warp -> LDS.128 broadcast, no bank pressure)
        const float* hb = &h_buf[s][kc * 32];
        float acc0 = 0.f, acc1 = 0.f;
        #pragma unroll
        for (int i = 0; i < 32; i += 4) {
            float4 h4 = *(const float4*)(hb + i);
            acc0 = fmaf(h4.x, a_reg[i + 0], acc0);
            acc1 = fmaf(h4.y, a_reg[i + 1], acc1);
            acc0 = fmaf(h4.z, a_reg[i + 2], acc0);
            acc1 = fmaf(h4.w, a_reg[i + 3], acc1);
        }
        part[kc][j] = acc0 + acc1;
        __syncthreads();                      // partials visible; h_buf[s] reads done

        if (tid < 64) {
            float z = part[0][j] + part[1][j] + part[2][j] + part[3][j]
                    + part[4][j] + part[5][j] + part[6][j] + part[7][j]
                    + xb_buf[s];
            float hn = tanhf(z);

            // Push next-h to slot s^1 of every CTA in the cluster (incl. self).
            // Skipped on the last step: nothing consumes it, and skipping it
            // means the final cluster barrier fully drains remote traffic.
            if (t + 1 < DT) {
                const uint32_t dst = hb_a[s ^ 1] + (uint32_t)colg * 4;
                #pragma unroll
                for (uint32_t c = 0; c < 4; ++c)
                    st_cluster_f32(mapa_u32(dst, c), hn);
            }

            hs_b[(size_t)t * DH] = hn;        // fire-and-forget for phase 3
            if (t + 2 < DT) xb_buf[s] = __ldg(&xb_b[(size_t)(t + 2) * DH]);
        }

        // Release our remote writes + acquire peers'; also fences slot reuse.
        cluster_arrive();
        cluster_wait();
    }
}

// ---------------- Launch ----------------
extern "C" void kernel_launch(void* const* d_in, const int* in_sizes, int n_in,
                              void* d_out, int out_size)
{
    const float* x  = (const float*)d_in[0];   // [32,2048,128]
    const float* A  = (const float*)d_in[1];   // [256,256]
    const float* Bm = (const float*)d_in[2];   // [128,256]
    const float* C  = (const float*)d_in[3];   // [256,256]
    float* out = (float*)d_out;                // [32,2048,256]

    // Phase 1: xb = x @ Bm
    {
        dim3 grid(DH / 64, (DB * DT) / 64);    // (4, 1024)
        gemm_xb_kernel<<<grid, 256>>>(x, Bm);
    }
    // Phase 2: sequential scan, one 4-CTA cluster per batch (128 CTAs resident)
    {
        scan_kernel<<<DB * 4, 512>>>(A);
    }
    // Phase 3: out = hs @ C
    {
        dim3 grid(DH / 64, (DB * DT) / 64);
        gemm_out_kernel<<<grid, 256>>>(C, out);
    }
}